// round 1
// baseline (speedup 1.0000x reference)
#include <cuda_runtime.h>
#include <math.h>

// Problem constants (fixed by setup_inputs)
#define NB   16
#define NH   76
#define NW   76
#define NCH  32           // 19 + NC
#define HW   (NH*NW)      // 5776
#define NL   21           // 2*NK + 3
#define TPB  256
#define BLK_PER_B ((HW + TPB - 1)/TPB)   // 23
#define NBLK (BLK_PER_B * NB)            // 368

__device__ float g_partials[NBLK];

__device__ __forceinline__ float fsigmoid(float x) {
    return 1.0f / (1.0f + __expf(-x));
}

__global__ void __launch_bounds__(TPB)
loss_kernel(const float* __restrict__ out,
            const float* __restrict__ dst,
            const float* __restrict__ tgt)
{
    __shared__ float s_gt[50 * 18];   // corners pre-scaled by (IMW, IMH)
    __shared__ int   s_gi[50];
    __shared__ int   s_gj[50];
    __shared__ float s_cls[50];
    __shared__ int   s_nv;
    __shared__ float s_red[TPB / 32];

    const int b   = blockIdx.y;
    const int tid = threadIdx.x;
    const float* T = tgt + (size_t)b * (50 * NL);

    // Precompute per-target data in shared
    for (int t = tid; t < 50; t += TPB) {
        const float* row = T + t * NL;
        float x = row[1];
        float y = row[2];
        s_gi[t]  = (int)(x * (float)NW);
        s_gj[t]  = (int)(y * (float)NH);
        s_cls[t] = row[0];
        #pragma unroll
        for (int k = 0; k < 9; k++) {
            s_gt[t * 18 + 2 * k    ] = row[1 + 2 * k] * 640.0f;
            s_gt[t * 18 + 2 * k + 1] = row[2 + 2 * k] * 480.0f;
        }
    }
    if (tid == 0) {
        int nv = 0;
        while (nv < 50 && T[nv * NL + 1] != 0.0f) nv++;
        s_nv = nv;
    }
    __syncthreads();
    const int nv = s_nv;

    float loss = 0.0f;
    const int cell = blockIdx.x * TPB + tid;
    if (cell < HW) {
        const int i = cell % NW;
        const int j = cell / NW;
        const float* O = out + (size_t)b * NCH * HW + cell;  // channel stride HW
        const float* D = dst + (size_t)b * NCH * HW + cell;

        // Load the 19 unconditionally-needed output channels
        float o[19];
        #pragma unroll
        for (int c = 0; c < 19; c++) o[c] = O[(size_t)c * HW];

        // coords: sigmoid on channels 0,1 only
        float coords[18];
        coords[0] = fsigmoid(o[0]);
        coords[1] = fsigmoid(o[1]);
        #pragma unroll
        for (int c = 2; c < 18; c++) coords[c] = o[c];
        const float conf = fsigmoid(o[18]);

        // Predicted corners, pre-scaled to pixels: ((coord + g)/n) * IM
        const float sX = 640.0f / (float)NW;
        const float sY = 480.0f / (float)NH;
        float pcx[9], pcy[9];
        #pragma unroll
        for (int k = 0; k < 9; k++) {
            pcx[k] = (coords[2 * k]     + (float)i) * sX;
            pcy[k] = (coords[2 * k + 1] + (float)j) * sY;
        }

        // cur = max over valid targets of mean corner confidence
        // c = (exp(2*(1 - d/80)) - 1)/(e^2 - 1) = A*exp(-0.025*d) - B  (if d < 80)
        const float TH2 = 80.0f * 80.0f;
        const float A   = 1.15651764274966576f;   // e^2/(e^2-1)
        const float Bc  = 0.15651764274966568f;   // 1/(e^2-1)
        float cur = 0.0f;
        for (int t = 0; t < nv; t++) {
            const float2* g = reinterpret_cast<const float2*>(s_gt + t * 18);
            float s = 0.0f;
            #pragma unroll
            for (int k = 0; k < 9; k++) {
                float2 gv = g[k];
                float dx = gv.x - pcx[k];
                float dy = gv.y - pcy[k];
                float d2 = fmaf(dx, dx, dy * dy);
                float c  = fmaf(A, __expf(-0.025f * sqrtf(d2)), -Bc);
                s += (d2 < TH2) ? c : 0.0f;
            }
            cur = fmaxf(cur, s * (1.0f / 9.0f));
        }

        // Targeted? (last valid target writing this cell wins — matches .at.set order)
        bool targeted = false;
        int  tc = 0;
        for (int t = 0; t < nv; t++) {
            if (s_gi[t] == i && s_gj[t] == j) { targeted = true; tc = (int)s_cls[t]; }
        }

        // conf loss: conf_mask = 5 (obj) / 0 (cur>SIL) / 1 (noobj)
        const float tconf = fsigmoid(D[(size_t)18 * HW]);
        const float cm = targeted ? 5.0f : ((cur > 0.6f) ? 0.0f : 1.0f);
        const float dcf = conf - tconf;
        loss += 0.5f * dcf * dcf * cm;

        if (targeted) {
            // coord loss (COORD * 0.5 * sum sq diff over 18 channels)
            float lc = 0.0f;
            {
                float d0 = coords[0] - fsigmoid(D[0]);
                float d1 = coords[1] - fsigmoid(D[HW]);
                lc += d0 * d0 + d1 * d1;
            }
            #pragma unroll
            for (int c = 2; c < 18; c++) {
                float dd = coords[c] - D[(size_t)c * HW];
                lc += dd * dd;
            }
            loss += 0.5f * lc;

            // class CE = logsumexp(logits) - logits[tcls]  (precise math; rare cells)
            float l[13];
            #pragma unroll
            for (int c = 0; c < 13; c++) l[c] = O[(size_t)(19 + c) * HW];
            float m = l[0];
            #pragma unroll
            for (int c = 1; c < 13; c++) m = fmaxf(m, l[c]);
            float se = 0.0f;
            #pragma unroll
            for (int c = 0; c < 13; c++) se += expf(l[c] - m);
            loss += (m + logf(se)) - l[tc];
        }
    }

    // Deterministic block reduction
    #pragma unroll
    for (int off = 16; off; off >>= 1)
        loss += __shfl_down_sync(0xffffffffu, loss, off);
    if ((tid & 31) == 0) s_red[tid >> 5] = loss;
    __syncthreads();
    if (tid < (TPB / 32)) {
        float v = s_red[tid];
        #pragma unroll
        for (int off = (TPB / 64); off; off >>= 1)
            v += __shfl_down_sync(0xffu, v, off);
        if (tid == 0)
            g_partials[blockIdx.y * BLK_PER_B + blockIdx.x] = v;
    }
}

__global__ void reduce_kernel(float* __restrict__ outp)
{
    float s = 0.0f;
    for (int idx = threadIdx.x; idx < NBLK; idx += 32)
        s += g_partials[idx];
    #pragma unroll
    for (int off = 16; off; off >>= 1)
        s += __shfl_down_sync(0xffffffffu, s, off);
    if (threadIdx.x == 0) outp[0] = s;
}

extern "C" void kernel_launch(void* const* d_in, const int* in_sizes, int n_in,
                              void* d_out, int out_size)
{
    const float* out = (const float*)d_in[0];
    const float* dst = (const float*)d_in[1];
    const float* tgt = (const float*)d_in[2];
    (void)in_sizes; (void)n_in; (void)out_size;

    dim3 grid(BLK_PER_B, NB);
    loss_kernel<<<grid, TPB>>>(out, dst, tgt);
    reduce_kernel<<<1, 32>>>((float*)d_out);
}

// round 4
// speedup vs baseline: 1.0236x; 1.0236x over previous
#include <cuda_runtime.h>
#include <math.h>

// Problem constants (fixed by setup_inputs)
#define NB    16
#define NH    76
#define NW    76
#define NCH   32          // 19 + NC
#define HW    (NH*NW)     // 5776
#define NL    21          // 2*NK + 3
#define TILE  16
#define GX    ((NW + TILE - 1) / TILE)   // 5
#define GY    ((NH + TILE - 1) / TILE)   // 5
#define TPB   (TILE * TILE)              // 256
#define NBLK  (GX * GY * NB)             // 400

__device__ float        g_partials[NBLK];
__device__ unsigned int g_count;   // zero-init at load; decremented by NBLK by last block

__device__ __forceinline__ float fsigmoid(float x) {
    return 1.0f / (1.0f + __expf(-x));
}

__global__ void __launch_bounds__(TPB)
loss_kernel(const float* __restrict__ out,
            const float* __restrict__ dst,
            const float* __restrict__ tgt,
            float* __restrict__ res)
{
    __shared__ float s_gt[50 * 18];   // corners pre-scaled to pixels
    __shared__ int   s_gi[50];
    __shared__ int   s_gj[50];
    __shared__ float s_cls[50];
    __shared__ int   s_nv;
    __shared__ float s_red[TPB / 32];
    __shared__ bool  s_last;

    const int b   = blockIdx.z;
    const int tid = threadIdx.x;
    const float* T = tgt + (size_t)b * (50 * NL);

    // Per-target tables in shared
    for (int t = tid; t < 50; t += TPB) {
        const float* row = T + t * NL;
        s_gi[t]  = (int)(row[1] * (float)NW);
        s_gj[t]  = (int)(row[2] * (float)NH);
        s_cls[t] = row[0];
        #pragma unroll
        for (int k = 0; k < 9; k++) {
            s_gt[t * 18 + 2 * k    ] = row[1 + 2 * k] * 640.0f;
            s_gt[t * 18 + 2 * k + 1] = row[2 + 2 * k] * 480.0f;
        }
    }
    if (tid == 0) {
        int nv = 0;
        while (nv < 50 && T[nv * NL + 1] != 0.0f) nv++;
        s_nv = nv;
    }
    __syncthreads();
    const int nv = s_nv;

    // 2D tile mapping: warp = 16x2 cell patch -> warp-coherent distance culls
    const int i = blockIdx.x * TILE + (tid & (TILE - 1));
    const int j = blockIdx.y * TILE + (tid >> 4);

    float loss = 0.0f;
    {
        const int cell = j * NW + i;               // i<76, j<76 always (5*16=80>76 only when idx>=76)
        const bool inb = (i < NW) && (j < NH);
        const float* O = out + (size_t)b * NCH * HW + (inb ? cell : 0);
        const float* D = dst + (size_t)b * NCH * HW + (inb ? cell : 0);

        if (inb) {
            // 19 unconditionally-needed output channels
            float coords[18];
            coords[0] = fsigmoid(O[0]);
            coords[1] = fsigmoid(O[HW]);
            #pragma unroll
            for (int c = 2; c < 18; c++) coords[c] = O[(size_t)c * HW];
            const float conf = fsigmoid(O[(size_t)18 * HW]);

            // Predicted corners in pixels
            const float sX = 640.0f / (float)NW;
            const float sY = 480.0f / (float)NH;
            float pcx[9], pcy[9];
            #pragma unroll
            for (int k = 0; k < 9; k++) {
                pcx[k] = (coords[2 * k]     + (float)i) * sX;
                pcy[k] = (coords[2 * k + 1] + (float)j) * sY;
            }

            // Targeted? (last valid target writing this cell wins)
            bool targeted = false;
            int  tc = 0;
            for (int t = 0; t < nv; t++) {
                if (s_gi[t] == i && s_gj[t] == j) { targeted = true; tc = (int)s_cls[t]; }
            }

            // cur only matters when not targeted, and only vs threshold 0.6
            bool sil = false;
            if (!targeted) {
                const float TH2 = 80.0f * 80.0f;
                const float A   = 1.15651764274966576f;   // e^2/(e^2-1)
                const float Bc  = 0.15651764274966568f;   // 1/(e^2-1)
                float cur = 0.0f;
                for (int t = 0; t < nv; t++) {
                    const float2* g = reinterpret_cast<const float2*>(s_gt + t * 18);
                    float d2v[9];
                    bool  anynear = false;
                    #pragma unroll
                    for (int k = 0; k < 9; k++) {
                        float2 gv = g[k];
                        float dx = gv.x - pcx[k];
                        float dy = gv.y - pcy[k];
                        float d2 = fmaf(dx, dx, dy * dy);
                        d2v[k] = d2;
                        anynear = anynear || (d2 < TH2);
                    }
                    if (anynear) {   // expensive MUFU block only near targets
                        float s = 0.0f;
                        #pragma unroll
                        for (int k = 0; k < 9; k++) {
                            float c = fmaf(A, __expf(-0.025f * sqrtf(d2v[k])), -Bc);
                            s += (d2v[k] < TH2) ? c : 0.0f;
                        }
                        cur = fmaxf(cur, s * (1.0f / 9.0f));
                        if (cur > 0.6f) { sil = true; break; }
                    }
                }
            }

            // conf loss: mask = 5 (obj) / 0 (silenced) / 1 (noobj)
            const float tconf = fsigmoid(D[(size_t)18 * HW]);
            const float cm = targeted ? 5.0f : (sil ? 0.0f : 1.0f);
            const float dcf = conf - tconf;
            loss += 0.5f * dcf * dcf * cm;

            if (targeted) {
                // coord loss
                float lc = 0.0f;
                {
                    float d0 = coords[0] - fsigmoid(D[0]);
                    float d1 = coords[1] - fsigmoid(D[HW]);
                    lc += d0 * d0 + d1 * d1;
                }
                #pragma unroll
                for (int c = 2; c < 18; c++) {
                    float dd = coords[c] - D[(size_t)c * HW];
                    lc += dd * dd;
                }
                loss += 0.5f * lc;

                // class CE = logsumexp - logit[tcls] (precise math; rare cells)
                float l[13];
                #pragma unroll
                for (int c = 0; c < 13; c++) l[c] = O[(size_t)(19 + c) * HW];
                float m = l[0];
                #pragma unroll
                for (int c = 1; c < 13; c++) m = fmaxf(m, l[c]);
                float se = 0.0f;
                #pragma unroll
                for (int c = 0; c < 13; c++) se += expf(l[c] - m);
                loss += (m + logf(se)) - l[tc];
            }
        }
    }

    // Deterministic intra-block reduction
    #pragma unroll
    for (int off = 16; off; off >>= 1)
        loss += __shfl_down_sync(0xffffffffu, loss, off);
    if ((tid & 31) == 0) s_red[tid >> 5] = loss;
    __syncthreads();
    if (tid < (TPB / 32)) {
        float v = s_red[tid];
        #pragma unroll
        for (int off = (TPB / 64); off; off >>= 1)
            v += __shfl_down_sync(0xffu, v, off);
        if (tid == 0) {
            g_partials[(blockIdx.z * GY + blockIdx.y) * GX + blockIdx.x] = v;
            __threadfence();
            unsigned old = atomicAdd(&g_count, 1u);
            s_last = (old == (unsigned)(NBLK - 1));
        }
    }
    __syncthreads();

    // Last block performs the fixed-order final reduction (deterministic)
    if (s_last && tid < 32) {
        float s = 0.0f;
        for (int idx = tid; idx < NBLK; idx += 32)
            s += g_partials[idx];
        #pragma unroll
        for (int off = 16; off; off >>= 1)
            s += __shfl_down_sync(0xffffffffu, s, off);
        if (tid == 0) {
            res[0] = s;
            // Replay-safe reset: all NBLK increments have happened (we observed
            // old == NBLK-1 after our own), so subtracting NBLK is exact and
            // race-free regardless of how many graph replays follow.
            atomicSub(&g_count, (unsigned)NBLK);
        }
    }
}

extern "C" void kernel_launch(void* const* d_in, const int* in_sizes, int n_in,
                              void* d_out, int out_size)
{
    const float* out = (const float*)d_in[0];
    const float* dst = (const float*)d_in[1];
    const float* tgt = (const float*)d_in[2];
    (void)in_sizes; (void)n_in; (void)out_size;

    dim3 grid(GX, GY, NB);
    loss_kernel<<<grid, TPB>>>(out, dst, tgt, (float*)d_out);
}

// round 5
// speedup vs baseline: 2.0205x; 1.9739x over previous
#include <cuda_runtime.h>
#include <math.h>

// Problem constants (fixed by setup_inputs)
#define NB    16
#define NH    76
#define NW    76
#define NCH   32          // 19 + NC
#define HW    (NH*NW)     // 5776
#define NL    21          // 2*NK + 3
#define TX    16
#define TY    8
#define TPB   (TX*TY)                    // 128
#define GXN   ((NW + TX - 1) / TX)       // 5
#define GYN   ((NH + TY - 1) / TY)       // 10
#define NBLK  (GXN * GYN * NB)           // 800
#define GSTR  20                         // padded target-row stride (float4 aligned)

__device__ float        g_partials[NBLK];
__device__ unsigned int g_count;   // zero at load; last block subtracts NBLK (replay-safe)

__device__ __forceinline__ float fsigmoid(float x) {
    return 1.0f / (1.0f + __expf(-x));
}

__global__ void __launch_bounds__(TPB)
loss_kernel(const float* __restrict__ out,
            const float* __restrict__ dst,
            const float* __restrict__ tgt,
            float* __restrict__ res)
{
    __shared__ float    s_gt[50 * GSTR];   // corners pre-scaled to pixels, padded rows
    __shared__ unsigned s_mask[2];
    __shared__ int      s_map[TPB];        // packed (t+1)<<8 | cls for targeted cells
    __shared__ float    s_red[TPB / 32];
    __shared__ bool     s_last;

    const int b   = blockIdx.z;
    const int tid = threadIdx.x;
    const float* T = tgt + (size_t)b * (50 * NL);

    s_map[tid] = 0;

    // Phase 1: per-target preprocessing (thread t handles target t) + validity ballot
    float xv = 0.0f;
    int my_gi = 0, my_gj = 0, my_cls = 0;
    if (tid < 50) {
        const float* row = T + tid * NL;
        float x = row[1], y = row[2];
        xv = x;
        my_gi  = (int)(x * (float)NW);
        my_gj  = (int)(y * (float)NH);
        my_cls = (int)row[0];
        #pragma unroll
        for (int k = 0; k < 9; k++) {
            s_gt[tid * GSTR + 2 * k    ] = row[1 + 2 * k] * 640.0f;
            s_gt[tid * GSTR + 2 * k + 1] = row[2 + 2 * k] * 480.0f;
        }
    }
    if (tid < 64) {   // warps 0,1 fully — ballot legal
        unsigned m = __ballot_sync(0xffffffffu, xv != 0.0f);
        if ((tid & 31) == 0) s_mask[tid >> 5] = m;
    }
    __syncthreads();

    // nv = length of leading-valid prefix (cumprod semantics)
    const unsigned m0 = s_mask[0], m1 = s_mask[1];
    int nv;
    if (~m0)      nv = __ffs(~m0) - 1;
    else if (~m1) nv = 32 + __ffs(~m1) - 1;
    else          nv = 64;
    if (nv > 50) nv = 50;

    // Phase 2: targeted-cell map (last valid t wins == max t wins)
    const int bx0 = blockIdx.x * TX, by0 = blockIdx.y * TY;
    if (tid < nv) {
        int li = my_gi - bx0, lj = my_gj - by0;
        if (li >= 0 && li < TX && lj >= 0 && lj < TY)
            atomicMax(&s_map[lj * TX + li], ((tid + 1) << 8) | my_cls);
    }
    __syncthreads();

    const int i = bx0 + (tid & (TX - 1));
    const int j = by0 + (tid >> 4);

    float loss = 0.0f;
    if (i < NW && j < NH) {
        const float* O = out + (size_t)b * NCH * HW + j * NW + i;   // channel stride HW
        const float* D = dst + (size_t)b * NCH * HW + j * NW + i;

        // Predicted corners in pixels (coords not kept live; reloaded if targeted)
        const float sX = 640.0f / (float)NW;
        const float sY = 480.0f / (float)NH;
        float pcx[9], pcy[9];
        pcx[0] = (fsigmoid(O[0])  + (float)i) * sX;
        pcy[0] = (fsigmoid(O[HW]) + (float)j) * sY;
        #pragma unroll
        for (int k = 1; k < 9; k++) {
            pcx[k] = (O[(size_t)(2 * k    ) * HW] + (float)i) * sX;
            pcy[k] = (O[(size_t)(2 * k + 1) * HW] + (float)j) * sY;
        }
        const float conf = fsigmoid(O[(size_t)18 * HW]);

        const int  mpk      = s_map[tid];
        const bool targeted = (mpk != 0);
        const int  tc       = mpk & 0xff;

        // Silence test: cur>0.6 requires >=6 corners with d2<TH2 (c<=1 each).
        bool sil = false;
        const float TH2 = 6400.0f;
        for (int t = 0; t < nv; t++) {
            const float4* g4 = reinterpret_cast<const float4*>(s_gt + t * GSTR);
            float4 ga = g4[0], gb = g4[1], gc = g4[2], gd = g4[3];
            float2 ge = *reinterpret_cast<const float2*>(s_gt + t * GSTR + 16);
            float d2[9];
            float dx, dy;
            dx = ga.x - pcx[0]; dy = ga.y - pcy[0]; d2[0] = fmaf(dx, dx, dy * dy);
            dx = ga.z - pcx[1]; dy = ga.w - pcy[1]; d2[1] = fmaf(dx, dx, dy * dy);
            dx = gb.x - pcx[2]; dy = gb.y - pcy[2]; d2[2] = fmaf(dx, dx, dy * dy);
            dx = gb.z - pcx[3]; dy = gb.w - pcy[3]; d2[3] = fmaf(dx, dx, dy * dy);
            dx = gc.x - pcx[4]; dy = gc.y - pcy[4]; d2[4] = fmaf(dx, dx, dy * dy);
            dx = gc.z - pcx[5]; dy = gc.w - pcy[5]; d2[5] = fmaf(dx, dx, dy * dy);
            dx = gd.x - pcx[6]; dy = gd.y - pcy[6]; d2[6] = fmaf(dx, dx, dy * dy);
            dx = gd.z - pcx[7]; dy = gd.w - pcy[7]; d2[7] = fmaf(dx, dx, dy * dy);
            dx = ge.x - pcx[8]; dy = ge.y - pcy[8]; d2[8] = fmaf(dx, dx, dy * dy);
            int cnt = (d2[0] < TH2) + (d2[1] < TH2) + (d2[2] < TH2)
                    + (d2[3] < TH2) + (d2[4] < TH2) + (d2[5] < TH2)
                    + (d2[6] < TH2) + (d2[7] < TH2) + (d2[8] < TH2);
            if (cnt >= 6) {   // ~never with this data; precise math here
                float s = 0.0f;
                #pragma unroll
                for (int k = 0; k < 9; k++) {
                    float dist = sqrtf(d2[k]);
                    float c = (expf(2.0f * (1.0f - dist * (1.0f / 80.0f))) - 1.0f)
                              * (1.0f / 6.3890560989306495f);   // 1/(e^2-1)
                    s += (dist < 80.0f) ? c : 0.0f;
                }
                if (s * (1.0f / 9.0f) > 0.6f) { sil = true; break; }
            }
        }

        // conf loss: mask = 5 (obj) / 0 (silenced) / 1 (noobj)
        const float tconf = fsigmoid(D[(size_t)18 * HW]);
        const float cm  = targeted ? 5.0f : (sil ? 0.0f : 1.0f);
        const float dcf = conf - tconf;
        loss = 0.5f * dcf * dcf * cm;

        if (targeted) {   // rare (~1 cell per target)
            float lc = 0.0f;
            {
                float d0 = fsigmoid(O[0])  - fsigmoid(D[0]);
                float d1 = fsigmoid(O[HW]) - fsigmoid(D[HW]);
                lc += d0 * d0 + d1 * d1;
            }
            #pragma unroll
            for (int c = 2; c < 18; c++) {
                float dd = O[(size_t)c * HW] - D[(size_t)c * HW];
                lc += dd * dd;
            }
            loss += 0.5f * lc;

            // class CE = logsumexp(logits) - logits[tcls]
            float l[13];
            #pragma unroll
            for (int c = 0; c < 13; c++) l[c] = O[(size_t)(19 + c) * HW];
            float mx = l[0];
            #pragma unroll
            for (int c = 1; c < 13; c++) mx = fmaxf(mx, l[c]);
            float se = 0.0f;
            #pragma unroll
            for (int c = 0; c < 13; c++) se += expf(l[c] - mx);
            loss += (mx + logf(se)) - l[tc];
        }
    }

    // Deterministic intra-block reduction (4 warps)
    #pragma unroll
    for (int off = 16; off; off >>= 1)
        loss += __shfl_down_sync(0xffffffffu, loss, off);
    if ((tid & 31) == 0) s_red[tid >> 5] = loss;
    __syncthreads();
    if (tid == 0) {
        float v = s_red[0] + s_red[1] + s_red[2] + s_red[3];
        g_partials[(blockIdx.z * GYN + blockIdx.y) * GXN + blockIdx.x] = v;
        __threadfence();
        unsigned old = atomicAdd(&g_count, 1u);
        s_last = (old == (unsigned)(NBLK - 1));
    }
    __syncthreads();

    // Last block: fixed-order final reduction (deterministic)
    if (s_last && tid < 32) {
        float s = 0.0f;
        for (int idx = tid; idx < NBLK; idx += 32)
            s += g_partials[idx];
        #pragma unroll
        for (int off = 16; off; off >>= 1)
            s += __shfl_down_sync(0xffffffffu, s, off);
        if (tid == 0) {
            res[0] = s;
            atomicSub(&g_count, (unsigned)NBLK);   // replay-safe reset
        }
    }
}

extern "C" void kernel_launch(void* const* d_in, const int* in_sizes, int n_in,
                              void* d_out, int out_size)
{
    const float* out = (const float*)d_in[0];
    const float* dst = (const float*)d_in[1];
    const float* tgt = (const float*)d_in[2];
    (void)in_sizes; (void)n_in; (void)out_size;

    dim3 grid(GXN, GYN, NB);
    loss_kernel<<<grid, TPB>>>(out, dst, tgt, (float*)d_out);
}

// round 6
// speedup vs baseline: 2.7557x; 1.3639x over previous
#include <cuda_runtime.h>
#include <math.h>

// Problem constants (fixed by setup_inputs)
#define NB    16
#define NH    76
#define NW    76
#define NCH   32          // 19 + NC
#define HW    (NH*NW)     // 5776
#define NL    21          // 2*NK + 3
#define TX    16
#define TY    8
#define TPB   (TX*TY)                    // 128
#define GXN   ((NW + TX - 1) / TX)       // 5
#define GYN   ((NH + TY - 1) / TY)       // 10
#define NBLK  (GXN * GYN * NB)           // 800
#define GSTR  22                         // padded target-row stride (8B-aligned float2, low bank conflict)

__device__ float        g_partials[NBLK];
__device__ unsigned int g_count;   // zero at load; last block subtracts NBLK (replay-safe)

__device__ __forceinline__ float fsigmoid(float x) {
    return 1.0f / (1.0f + __expf(-x));
}
// order-preserving float <-> uint maps (total order), for redux.sync min/max on floats
__device__ __forceinline__ unsigned f2o(float f) {
    unsigned u = __float_as_uint(f);
    return (u & 0x80000000u) ? ~u : (u | 0x80000000u);
}
__device__ __forceinline__ float o2f(unsigned u) {
    return __uint_as_float((u & 0x80000000u) ? (u & 0x7fffffffu) : ~u);
}

__global__ void __launch_bounds__(TPB)
loss_kernel(const float* __restrict__ out,
            const float* __restrict__ dst,
            const float* __restrict__ tgt,
            float* __restrict__ res)
{
    __shared__ float    s_gt[50 * GSTR];   // corners pre-scaled to pixels
    __shared__ unsigned s_mask[2];
    __shared__ int      s_map[TPB];        // packed (t+1)<<8 | cls for targeted cells
    __shared__ float    s_red[TPB / 32];
    __shared__ bool     s_last;

    const int b    = blockIdx.z;
    const int tid  = threadIdx.x;
    const int lane = tid & 31;
    const float* T = tgt + (size_t)b * (50 * NL);

    s_map[tid] = 0;

    // Phase 1: per-target preprocessing (thread t handles target t) + validity ballot
    float xv = 0.0f;
    int my_gi = 0, my_gj = 0, my_cls = 0;
    if (tid < 50) {
        const float* row = T + tid * NL;
        float x = row[1], y = row[2];
        xv = x;
        my_gi  = (int)(x * (float)NW);
        my_gj  = (int)(y * (float)NH);
        my_cls = (int)row[0];
        #pragma unroll
        for (int k = 0; k < 9; k++) {
            s_gt[tid * GSTR + 2 * k    ] = row[1 + 2 * k] * 640.0f;
            s_gt[tid * GSTR + 2 * k + 1] = row[2 + 2 * k] * 480.0f;
        }
    }
    if (tid < 64) {   // warps 0,1 fully — ballot legal
        unsigned m = __ballot_sync(0xffffffffu, xv != 0.0f);
        if (lane == 0) s_mask[tid >> 5] = m;
    }
    __syncthreads();

    // nv = length of leading-valid prefix (cumprod semantics)
    const unsigned m0v = s_mask[0], m1v = s_mask[1];
    int nv;
    if (~m0v)      nv = __ffs(~m0v) - 1;
    else if (~m1v) nv = 32 + __ffs(~m1v) - 1;
    else           nv = 64;
    if (nv > 50) nv = 50;

    // Phase 2: targeted-cell map (last valid t wins == max t wins)
    const int bx0 = blockIdx.x * TX, by0 = blockIdx.y * TY;
    if (tid < nv) {
        int li = my_gi - bx0, lj = my_gj - by0;
        if (li >= 0 && li < TX && lj >= 0 && lj < TY)
            atomicMax(&s_map[lj * TX + li], ((tid + 1) << 8) | my_cls);
    }
    __syncthreads();

    const int  i   = bx0 + (tid & (TX - 1));
    const int  j   = by0 + (tid >> 4);
    const bool inb = (i < NW) && (j < NH);
    const int  cell = inb ? (j * NW + i) : 0;           // clamped (loads legal)
    const float* O = out + (size_t)b * NCH * HW + cell; // channel stride HW
    const float* D = dst + (size_t)b * NCH * HW + cell;

    const float sX = 640.0f / (float)NW;
    const float sY = 480.0f / (float)NH;

    // Phase 3: per-warp exact bounding boxes of predicted corners (redux.sync)
    float lox[9], hix[9], loy[9], hiy[9];
    #pragma unroll
    for (int k = 0; k < 9; k++) {
        float ox = O[(size_t)(2 * k    ) * HW];
        float oy = O[(size_t)(2 * k + 1) * HW];
        if (k == 0) { ox = fsigmoid(ox); oy = fsigmoid(oy); }
        float px = (ox + (float)i) * sX;
        float py = (oy + (float)j) * sY;
        unsigned kx = inb ? f2o(px) : 0u;   // max-neutral
        unsigned ky = inb ? f2o(py) : 0u;
        unsigned kxm = inb ? f2o(px) : 0xffffffffu;  // min-neutral
        unsigned kym = inb ? f2o(py) : 0xffffffffu;
        lox[k] = o2f(__reduce_min_sync(0xffffffffu, kxm)) - 80.5f;
        hix[k] = o2f(__reduce_max_sync(0xffffffffu, kx )) + 80.5f;
        loy[k] = o2f(__reduce_min_sync(0xffffffffu, kym)) - 80.5f;
        hiy[k] = o2f(__reduce_max_sync(0xffffffffu, ky )) + 80.5f;
    }

    // Phase 4: per-warp target cull — survivor iff >=6 corners inside expanded boxes
    unsigned sm0, sm1;
    {
        int c0 = 0, c1 = 0;
        const float* g0 = s_gt + lane * GSTR;
        const float* g1 = s_gt + (lane + 32) * GSTR;
        bool a0 = (lane      < nv);
        bool a1 = (lane + 32 < nv);
        #pragma unroll
        for (int k = 0; k < 9; k++) {
            float2 ga = a0 ? *reinterpret_cast<const float2*>(g0 + 2 * k) : make_float2(-1e30f, -1e30f);
            float2 gb = a1 ? *reinterpret_cast<const float2*>(g1 + 2 * k) : make_float2(-1e30f, -1e30f);
            c0 += (ga.x >= lox[k] && ga.x <= hix[k] && ga.y >= loy[k] && ga.y <= hiy[k]) ? 1 : 0;
            c1 += (gb.x >= lox[k] && gb.x <= hix[k] && gb.y >= loy[k] && gb.y <= hiy[k]) ? 1 : 0;
        }
        sm0 = __ballot_sync(0xffffffffu, a0 && c0 >= 6);
        sm1 = __ballot_sync(0xffffffffu, a1 && c1 >= 6);
    }

    // Phase 5: exact evaluation for rare survivors (warp-uniform branch)
    bool sil = false;
    unsigned long long smask = (((unsigned long long)sm1) << 32) | sm0;
    if (smask) {
        float pcx[9], pcy[9];
        pcx[0] = (fsigmoid(O[0])  + (float)i) * sX;
        pcy[0] = (fsigmoid(O[HW]) + (float)j) * sY;
        #pragma unroll
        for (int k = 1; k < 9; k++) {
            pcx[k] = (O[(size_t)(2 * k    ) * HW] + (float)i) * sX;
            pcy[k] = (O[(size_t)(2 * k + 1) * HW] + (float)j) * sY;
        }
        do {
            int t = __ffsll(smask) - 1;
            smask &= smask - 1;
            const float* gp = s_gt + t * GSTR;
            float d2[9];
            int cnt = 0;
            #pragma unroll
            for (int k = 0; k < 9; k++) {
                float2 gv = *reinterpret_cast<const float2*>(gp + 2 * k);
                float dx = gv.x - pcx[k];
                float dy = gv.y - pcy[k];
                d2[k] = fmaf(dx, dx, dy * dy);
                cnt += (d2[k] < 6400.0f) ? 1 : 0;
            }
            if (cnt >= 6) {   // precise math; essentially never taken
                float s = 0.0f;
                #pragma unroll
                for (int k = 0; k < 9; k++) {
                    float dist = sqrtf(d2[k]);
                    float c = (expf(2.0f * (1.0f - dist * (1.0f / 80.0f))) - 1.0f)
                              * (1.0f / 6.3890560989306495f);   // 1/(e^2-1)
                    s += (dist < 80.0f) ? c : 0.0f;
                }
                if (s * (1.0f / 9.0f) > 0.6f) sil = true;
            }
        } while (smask);
    }

    // Phase 6: losses
    float loss = 0.0f;
    if (inb) {
        const float conf  = fsigmoid(O[(size_t)18 * HW]);
        const float tconf = fsigmoid(D[(size_t)18 * HW]);
        const int   mpk      = s_map[tid];
        const bool  targeted = (mpk != 0);
        const int   tc       = mpk & 0xff;
        const float cm  = targeted ? 5.0f : (sil ? 0.0f : 1.0f);
        const float dcf = conf - tconf;
        loss = 0.5f * dcf * dcf * cm;

        if (targeted) {   // rare (~1 cell per target)
            float lc = 0.0f;
            {
                float d0 = fsigmoid(O[0])  - fsigmoid(D[0]);
                float d1 = fsigmoid(O[HW]) - fsigmoid(D[HW]);
                lc += d0 * d0 + d1 * d1;
            }
            #pragma unroll
            for (int c = 2; c < 18; c++) {
                float dd = O[(size_t)c * HW] - D[(size_t)c * HW];
                lc += dd * dd;
            }
            loss += 0.5f * lc;

            // class CE = logsumexp(logits) - logits[tcls]
            float l[13];
            #pragma unroll
            for (int c = 0; c < 13; c++) l[c] = O[(size_t)(19 + c) * HW];
            float mx = l[0];
            #pragma unroll
            for (int c = 1; c < 13; c++) mx = fmaxf(mx, l[c]);
            float se = 0.0f;
            #pragma unroll
            for (int c = 0; c < 13; c++) se += expf(l[c] - mx);
            loss += (mx + logf(se)) - l[tc];
        }
    }

    // Deterministic intra-block reduction (4 warps)
    #pragma unroll
    for (int off = 16; off; off >>= 1)
        loss += __shfl_down_sync(0xffffffffu, loss, off);
    if (lane == 0) s_red[tid >> 5] = loss;
    __syncthreads();
    if (tid == 0) {
        float v = s_red[0] + s_red[1] + s_red[2] + s_red[3];
        g_partials[(blockIdx.z * GYN + blockIdx.y) * GXN + blockIdx.x] = v;
        __threadfence();
        unsigned old = atomicAdd(&g_count, 1u);
        s_last = (old == (unsigned)(NBLK - 1));
    }
    __syncthreads();

    // Last block: fixed-order final reduction (deterministic)
    if (s_last && tid < 32) {
        float s = 0.0f;
        for (int idx = tid; idx < NBLK; idx += 32)
            s += g_partials[idx];
        #pragma unroll
        for (int off = 16; off; off >>= 1)
            s += __shfl_down_sync(0xffffffffu, s, off);
        if (tid == 0) {
            res[0] = s;
            atomicSub(&g_count, (unsigned)NBLK);   // replay-safe reset
        }
    }
}

extern "C" void kernel_launch(void* const* d_in, const int* in_sizes, int n_in,
                              void* d_out, int out_size)
{
    const float* out = (const float*)d_in[0];
    const float* dst = (const float*)d_in[1];
    const float* tgt = (const float*)d_in[2];
    (void)in_sizes; (void)n_in; (void)out_size;

    dim3 grid(GXN, GYN, NB);
    loss_kernel<<<grid, TPB>>>(out, dst, tgt, (float*)d_out);
}